// round 5
// baseline (speedup 1.0000x reference)
#include <cuda_runtime.h>

// ---------------- problem constants ----------------
#define TOK    32768      // B*H*W * n_seg tokens
#define BHW    8192
#define NSEG   4
#define INDIM  1536       // SEG*D
#define HID    768        // (SEG/2)*D
#define NHEAD  8
#define HD     96
// x layout strides (B=8,T=96,H=32,W=32,D=64), flat index:
//   b*6291456 + t*65536 + hw*64 + d,  hw = h*32+w, t = nseg*24 + p, feature e = p*64+d

// ---------------- scratch (static device arrays; no allocs) ----------------
__device__ float g_q[(size_t)TOK * HID];
__device__ float g_k[(size_t)TOK * HID];
__device__ float g_v[(size_t)TOK * HID];
__device__ float g_o[(size_t)TOK * HID];

// packed fp32x2 FMA (Blackwell FFMA2 — only reachable via PTX)
__device__ __forceinline__ void fma2(unsigned long long& c, unsigned long long a, unsigned long long b) {
    asm("fma.rn.f32x2 %0, %1, %2, %0;" : "+l"(c) : "l"(a), "l"(b));
}

// =====================================================================
// Kernel 1: QKV GEMM.  C[z][m][n] = sum_k A[m][k] * W_z[k][n]
// A gathered from x.  Tile 128x128x8, 256 threads, 8x8/thread via f32x2.
// =====================================================================
__global__ __launch_bounds__(256, 2)
void gemm_qkv(const float* __restrict__ x,
              const float* __restrict__ Wq,
              const float* __restrict__ Wk,
              const float* __restrict__ Wv)
{
    __shared__ float AsD[8][256];   // A tile transposed, each value DUPLICATED: [k][2m]=[k][2m+1]
    __shared__ float Bs[8][128];

    const int z = blockIdx.z;
    const float* __restrict__ W = (z == 0) ? Wq : ((z == 1) ? Wk : Wv);
    float* __restrict__ C = (z == 0) ? g_q : ((z == 1) ? g_k : g_v);

    const int tid = threadIdx.x;
    const int m0 = blockIdx.y * 128;
    const int n0 = blockIdx.x * 128;

    // global A load mapping: row = tid>>1, k-sub = (tid&1)*4
    const int lr = tid >> 1;
    const int lk = (tid & 1) * 4;
    const int m   = m0 + lr;
    const int bhw = m >> 2, nseg = m & 3;
    const int b   = bhw >> 10, hw = bhw & 1023;
    const long baseA = ((long)(b * 96 + nseg * 24) * 1024 + hw) * 64;

    // global B load mapping: k row = tid>>5, col4 = (tid&31)*4
    const int kb = tid >> 5;
    const int nb = (tid & 31) * 4;

    // compute mapping
    const int u = tid & 15;     // column-pair lane
    const int g = tid >> 4;     // row group

    unsigned long long acc[8][4];
    #pragma unroll
    for (int i = 0; i < 8; i++)
        #pragma unroll
        for (int j = 0; j < 4; j++) acc[i][j] = 0ull;

    const int NK = INDIM / 8;   // 192

    // prologue: load tile 0 into registers
    float4 ra, rb;
    {
        int k = lk, p = k >> 6, d = k & 63;
        ra = *(const float4*)(x + baseA + (long)p * 65536 + d);
        rb = *(const float4*)(W + (long)kb * HID + n0 + nb);
    }

    for (int kt = 0; kt < NK; kt++) {
        // stage to smem (A duplicated)
        AsD[lk + 0][2 * lr] = ra.x; AsD[lk + 0][2 * lr + 1] = ra.x;
        AsD[lk + 1][2 * lr] = ra.y; AsD[lk + 1][2 * lr + 1] = ra.y;
        AsD[lk + 2][2 * lr] = ra.z; AsD[lk + 2][2 * lr + 1] = ra.z;
        AsD[lk + 3][2 * lr] = ra.w; AsD[lk + 3][2 * lr + 1] = ra.w;
        *(float4*)&Bs[kb][nb] = rb;
        __syncthreads();

        if (kt + 1 < NK) {   // prefetch next tile into registers
            int k = (kt + 1) * 8 + lk, p = k >> 6, d = k & 63;
            ra = *(const float4*)(x + baseA + (long)p * 65536 + d);
            rb = *(const float4*)(W + (long)((kt + 1) * 8 + kb) * HID + n0 + nb);
        }

        #pragma unroll
        for (int kk = 0; kk < 8; kk++) {
            unsigned long long av[8], bv[4];
            // rows 4g..4g+3 live at duplicated float index 8g..8g+7
            const ulonglong2* pa0 = (const ulonglong2*)&AsD[kk][8 * g];
            ulonglong2 t0 = pa0[0], t1 = pa0[1];
            // rows 64+4g..64+4g+3 live at duplicated float index 128+8g..128+8g+7
            const ulonglong2* pa1 = (const ulonglong2*)&AsD[kk][128 + 8 * g];
            ulonglong2 t2 = pa1[0], t3 = pa1[1];
            av[0] = t0.x; av[1] = t0.y; av[2] = t1.x; av[3] = t1.y;
            av[4] = t2.x; av[5] = t2.y; av[6] = t3.x; av[7] = t3.y;
            #pragma unroll
            for (int j = 0; j < 4; j++)
                bv[j] = *(const unsigned long long*)&Bs[kk][2 * u + 32 * j];
            #pragma unroll
            for (int i = 0; i < 8; i++)
                #pragma unroll
                for (int j = 0; j < 4; j++)
                    fma2(acc[i][j], av[i], bv[j]);
        }
        __syncthreads();
    }

    // epilogue: contiguous store to C
    #pragma unroll
    for (int i = 0; i < 8; i++) {
        int r = (i < 4) ? (g * 4 + i) : (64 + g * 4 + (i - 4));
        long row = (long)(m0 + r) * HID;
        #pragma unroll
        for (int j = 0; j < 4; j++) {
            int c = n0 + 2 * u + 32 * j;
            *(float2*)(C + row + c) = *(float2*)&acc[i][j];
        }
    }
}

// =====================================================================
// Kernel 2: RoPE + tiny attention.  One CTA per bhw row, one warp per head.
// =====================================================================
__global__ __launch_bounds__(256)
void attn_kernel(const float* __restrict__ fcos, const float* __restrict__ fsin)
{
    __shared__ float sq[NSEG][HID];
    __shared__ float sk[NSEG][HID];
    __shared__ float sv[NSEG][HID];

    const int bhw = blockIdx.x;
    const int tid = threadIdx.x;
    const long base = (long)bhw * NSEG * HID;

    // load q,k with RoPE; v straight.  1536 pairs total.
    for (int idx = tid; idx < NSEG * (HID / 2); idx += 256) {
        int i = idx / (HID / 2);
        int j = idx - i * (HID / 2);
        float c = fcos[i * (HID / 2) + j];
        float s = fsin[i * (HID / 2) + j];
        float2 q2 = *(const float2*)(g_q + base + (long)i * HID + 2 * j);
        float2 k2 = *(const float2*)(g_k + base + (long)i * HID + 2 * j);
        sq[i][2 * j]     = q2.x * c - q2.y * s;
        sq[i][2 * j + 1] = q2.x * s + q2.y * c;
        sk[i][2 * j]     = k2.x * c - k2.y * s;
        sk[i][2 * j + 1] = k2.x * s + k2.y * c;
        float2 v2 = *(const float2*)(g_v + base + (long)i * HID + 2 * j);
        *(float2*)&sv[i][2 * j] = v2;
    }
    __syncthreads();

    const int w = tid >> 5;         // head
    const int lane = tid & 31;
    const int cb = w * HD;

    // scores[i][j] = q_i . k_j  (length 96, 3 elems per lane)
    float sc[4][4];
    #pragma unroll
    for (int i = 0; i < 4; i++)
        #pragma unroll
        for (int j = 0; j < 4; j++) {
            float p = 0.f;
            #pragma unroll
            for (int t = 0; t < 3; t++) {
                int d = lane + 32 * t;
                p += sq[i][cb + d] * sk[j][cb + d];
            }
            sc[i][j] = p;
        }
    // butterfly all-reduce within warp
    #pragma unroll
    for (int i = 0; i < 4; i++)
        #pragma unroll
        for (int j = 0; j < 4; j++)
            #pragma unroll
            for (int off = 16; off > 0; off >>= 1)
                sc[i][j] += __shfl_xor_sync(0xffffffffu, sc[i][j], off);

    const float scale = 0.10206207261596577f;   // 1/sqrt(96)
    float attn[4][4];
    #pragma unroll
    for (int i = 0; i < 4; i++) {
        float mx = -1e30f;
        #pragma unroll
        for (int j = 0; j < 4; j++) { sc[i][j] *= scale; mx = fmaxf(mx, sc[i][j]); }
        float sum = 0.f;
        #pragma unroll
        for (int j = 0; j < 4; j++) { attn[i][j] = expf(sc[i][j] - mx); sum += attn[i][j]; }
        float inv = 1.f / sum;
        #pragma unroll
        for (int j = 0; j < 4; j++) attn[i][j] *= inv;
    }

    // o = attn @ v
    #pragma unroll
    for (int i = 0; i < 4; i++) {
        #pragma unroll
        for (int t = 0; t < 3; t++) {
            int d = lane + 32 * t;
            float o = 0.f;
            #pragma unroll
            for (int j = 0; j < 4; j++) o += attn[i][j] * sv[j][cb + d];
            g_o[base + (long)i * HID + cb + d] = o;
        }
    }
}

// =====================================================================
// Kernel 3: output GEMM.  out[m][e] = sum_k o[m][k]*Wo[k][e] + bo[e],
// scatter-stored back into (B,T,H,W,D) layout.
// =====================================================================
__global__ __launch_bounds__(256, 2)
void gemm_out(const float* __restrict__ Wo,
              const float* __restrict__ bo,
              float* __restrict__ out)
{
    __shared__ float AsD[8][256];
    __shared__ float Bs[8][128];

    const int tid = threadIdx.x;
    const int m0 = blockIdx.y * 128;
    const int n0 = blockIdx.x * 128;

    const int lr = tid >> 1;
    const int lk = (tid & 1) * 4;
    const int kb = tid >> 5;
    const int nb = (tid & 31) * 4;
    const int u = tid & 15;
    const int g = tid >> 4;

    unsigned long long acc[8][4];
    #pragma unroll
    for (int i = 0; i < 8; i++)
        #pragma unroll
        for (int j = 0; j < 4; j++) acc[i][j] = 0ull;

    const int NK = HID / 8;   // 96

    float4 ra, rb;
    ra = *(const float4*)(g_o + (long)(m0 + lr) * HID + lk);
    rb = *(const float4*)(Wo + (long)kb * INDIM + n0 + nb);

    for (int kt = 0; kt < NK; kt++) {
        AsD[lk + 0][2 * lr] = ra.x; AsD[lk + 0][2 * lr + 1] = ra.x;
        AsD[lk + 1][2 * lr] = ra.y; AsD[lk + 1][2 * lr + 1] = ra.y;
        AsD[lk + 2][2 * lr] = ra.z; AsD[lk + 2][2 * lr + 1] = ra.z;
        AsD[lk + 3][2 * lr] = ra.w; AsD[lk + 3][2 * lr + 1] = ra.w;
        *(float4*)&Bs[kb][nb] = rb;
        __syncthreads();

        if (kt + 1 < NK) {
            ra = *(const float4*)(g_o + (long)(m0 + lr) * HID + (kt + 1) * 8 + lk);
            rb = *(const float4*)(Wo + (long)((kt + 1) * 8 + kb) * INDIM + n0 + nb);
        }

        #pragma unroll
        for (int kk = 0; kk < 8; kk++) {
            unsigned long long av[8], bv[4];
            const ulonglong2* pa0 = (const ulonglong2*)&AsD[kk][8 * g];
            ulonglong2 t0 = pa0[0], t1 = pa0[1];
            const ulonglong2* pa1 = (const ulonglong2*)&AsD[kk][128 + 8 * g];
            ulonglong2 t2 = pa1[0], t3 = pa1[1];
            av[0] = t0.x; av[1] = t0.y; av[2] = t1.x; av[3] = t1.y;
            av[4] = t2.x; av[5] = t2.y; av[6] = t3.x; av[7] = t3.y;
            #pragma unroll
            for (int j = 0; j < 4; j++)
                bv[j] = *(const unsigned long long*)&Bs[kk][2 * u + 32 * j];
            #pragma unroll
            for (int i = 0; i < 8; i++)
                #pragma unroll
                for (int j = 0; j < 4; j++)
                    fma2(acc[i][j], av[i], bv[j]);
        }
        __syncthreads();
    }

    // epilogue: +bias, scatter to (B,T,H,W,D)
    #pragma unroll
    for (int i = 0; i < 8; i++) {
        int r = (i < 4) ? (g * 4 + i) : (64 + g * 4 + (i - 4));
        int m = m0 + r;
        int bhw = m >> 2, nseg = m & 3;
        int b = bhw >> 10, hw = bhw & 1023;
        long baseO = ((long)(b * 96 + nseg * 24) * 1024 + hw) * 64;
        #pragma unroll
        for (int j = 0; j < 4; j++) {
            int e = n0 + 2 * u + 32 * j;
            int p = e >> 6, d = e & 63;
            float2 v = *(float2*)&acc[i][j];
            float2 bb = *(const float2*)(bo + e);
            v.x += bb.x; v.y += bb.y;
            *(float2*)(out + baseO + (long)p * 65536 + d) = v;
        }
    }
}

// =====================================================================
extern "C" void kernel_launch(void* const* d_in, const int* in_sizes, int n_in,
                              void* d_out, int out_size)
{
    const float* x  = (const float*)d_in[0];
    const float* fc = (const float*)d_in[1];
    const float* fs = (const float*)d_in[2];
    const float* Wq = (const float*)d_in[3];
    const float* Wk = (const float*)d_in[4];
    const float* Wv = (const float*)d_in[5];
    const float* Wo = (const float*)d_in[6];
    const float* bo = (const float*)d_in[7];
    float* out = (float*)d_out;

    gemm_qkv<<<dim3(HID / 128, TOK / 128, 3), 256>>>(x, Wq, Wk, Wv);
    attn_kernel<<<BHW, 256>>>(fc, fs);
    gemm_out<<<dim3(INDIM / 128, TOK / 128), 256>>>(Wo, bo, out);
}

// round 7
// speedup vs baseline: 2.6048x; 2.6048x over previous
#include <cuda_runtime.h>
#include <cuda_bf16.h>
#include <cstdint>

// ---------------- problem constants ----------------
#define TOK    32768
#define BHW    8192
#define NSEG   4
#define INDIM  1536
#define HID    768
#define NHEAD  8
#define HD     96

// ---------------- scratch ----------------
__device__ float g_q[(size_t)TOK * HID];
__device__ float g_k[(size_t)TOK * HID];
__device__ float g_v[(size_t)TOK * HID];
__device__ float g_o[(size_t)TOK * HID];
// transposed bf16 weights: [n][k] (N-major rows, K contiguous)
__device__ __nv_bfloat16 g_wq_hi[(size_t)HID * INDIM];
__device__ __nv_bfloat16 g_wq_lo[(size_t)HID * INDIM];
__device__ __nv_bfloat16 g_wk_hi[(size_t)HID * INDIM];
__device__ __nv_bfloat16 g_wk_lo[(size_t)HID * INDIM];
__device__ __nv_bfloat16 g_wv_hi[(size_t)HID * INDIM];
__device__ __nv_bfloat16 g_wv_lo[(size_t)HID * INDIM];
__device__ __nv_bfloat16 g_wo_hi[(size_t)INDIM * HID];
__device__ __nv_bfloat16 g_wo_lo[(size_t)INDIM * HID];

// ---------------- helpers ----------------
__device__ __forceinline__ uint32_t smem_u32(const void* p) {
    uint32_t a;
    asm("{ .reg .u64 t; cvta.to.shared.u64 t, %1; cvt.u32.u64 %0, t; }" : "=r"(a) : "l"(p));
    return a;
}

__device__ __forceinline__ void cp16(uint32_t dst, const void* src) {
    asm volatile("cp.async.cg.shared.global [%0], [%1], 16;" :: "r"(dst), "l"(src) : "memory");
}
#define CP_COMMIT() asm volatile("cp.async.commit_group;" ::: "memory")
#define CP_WAIT(n)  asm volatile("cp.async.wait_group %0;" :: "n"(n) : "memory")

#define LDSM_X4(r, a) \
    asm volatile("ldmatrix.sync.aligned.m8n8.x4.shared.b16 {%0,%1,%2,%3}, [%4];" \
        : "=r"((r)[0]), "=r"((r)[1]), "=r"((r)[2]), "=r"((r)[3]) : "r"(a))

__device__ __forceinline__ void mma16816(float* d, const uint32_t* a, uint32_t b0, uint32_t b1) {
    asm volatile("mma.sync.aligned.m16n8k16.row.col.f32.bf16.bf16.f32 "
        "{%0,%1,%2,%3}, {%4,%5,%6,%7}, {%8,%9}, {%0,%1,%2,%3};"
        : "+f"(d[0]), "+f"(d[1]), "+f"(d[2]), "+f"(d[3])
        : "r"(a[0]), "r"(a[1]), "r"(a[2]), "r"(a[3]), "r"(b0), "r"(b1));
}

// pack two floats to bf16 hi pair; return residuals
__device__ __forceinline__ uint32_t hi2(float a, float b, float& ra, float& rb) {
    __nv_bfloat16 ha = __float2bfloat16_rn(a), hb = __float2bfloat16_rn(b);
    ra = a - __bfloat162float(ha);
    rb = b - __bfloat162float(hb);
    return (uint32_t)(*(uint16_t*)&ha) | ((uint32_t)(*(uint16_t*)&hb) << 16);
}
__device__ __forceinline__ uint32_t lo2(float a, float b) {
    __nv_bfloat16 ha = __float2bfloat16_rn(a), hb = __float2bfloat16_rn(b);
    return (uint32_t)(*(uint16_t*)&ha) | ((uint32_t)(*(uint16_t*)&hb) << 16);
}

// =====================================================================
// weight conversion: W[k][n] fp32 -> Wt_hi/lo[n][k] bf16
// =====================================================================
__global__ void convert_qkv(const float* __restrict__ Wq,
                            const float* __restrict__ Wk,
                            const float* __restrict__ Wv)
{
    const int z = blockIdx.y;
    const float* W = (z == 0) ? Wq : ((z == 1) ? Wk : Wv);
    __nv_bfloat16* oh = (z == 0) ? g_wq_hi : ((z == 1) ? g_wk_hi : g_wv_hi);
    __nv_bfloat16* ol = (z == 0) ? g_wq_lo : ((z == 1) ? g_wk_lo : g_wv_lo);
    int idx = blockIdx.x * 256 + threadIdx.x;      // n*INDIM + k
    int n = idx / INDIM, k = idx - n * INDIM;
    float v = W[(size_t)k * HID + n];
    __nv_bfloat16 h = __float2bfloat16_rn(v);
    oh[idx] = h;
    ol[idx] = __float2bfloat16_rn(v - __bfloat162float(h));
}

__global__ void convert_wo(const float* __restrict__ Wo)
{
    int idx = blockIdx.x * 256 + threadIdx.x;      // e*HID + k
    int e = idx / HID, k = idx - e * HID;
    float v = Wo[(size_t)k * INDIM + e];
    __nv_bfloat16 h = __float2bfloat16_rn(v);
    g_wo_hi[idx] = h;
    g_wo_lo[idx] = __float2bfloat16_rn(v - __bfloat162float(h));
}

// =====================================================================
// Kernel 1: QKV GEMM, mma.sync bf16 split-3.
// grid (6, 256, 3), block 512.  CTA tile 128x128, K-chunk 16, 2 stages.
// =====================================================================
__global__ __launch_bounds__(512, 1) void gemm_qkv_mma(const float* __restrict__ x)
{
    __shared__ __nv_bfloat16 sAh[2][128][24];
    __shared__ __nv_bfloat16 sAl[2][128][24];
    __shared__ __nv_bfloat16 sBh[2][128][24];
    __shared__ __nv_bfloat16 sBl[2][128][24];

    const int tid = threadIdx.x;
    const int n0 = blockIdx.x * 128, m0 = blockIdx.y * 128, z = blockIdx.z;
    const __nv_bfloat16* Bhi = (z == 0) ? g_wq_hi : ((z == 1) ? g_wk_hi : g_wv_hi);
    const __nv_bfloat16* Blo = (z == 0) ? g_wq_lo : ((z == 1) ? g_wk_lo : g_wv_lo);
    float* C = (z == 0) ? g_q : ((z == 1) ? g_k : g_v);

    // ---- A loader mapping: row = tid>>2, seg = tid&3 (4 floats) ----
    const int arow = tid >> 2, aseg = tid & 3;
    long baseA;
    {
        int m = m0 + arow;
        int bhw = m >> 2, sg = m & 3, b = bhw >> 10, hw = bhw & 1023;
        baseA = ((long)(b * 96 + sg * 24) * 1024 + hw) * 64;
    }
    // ---- B loader mapping: op = tid>=256 (lo), row = (tid&255)>>1, half = tid&1
    const int bop = tid >> 8, brow = (tid & 255) >> 1, bhalf = tid & 1;
    const __nv_bfloat16* bsrc = bop ? Blo : Bhi;

    // ---- compute mapping ----
    const int wid = tid >> 5, lane = tid & 31;
    const int wm = wid & 3, wn = wid >> 2;
    // ldmatrix source addresses (halves offsets within a [128][24] plane)
    const int aldr = wm * 32 + (lane & 15);          // + mi*16
    const int aldc = (lane >> 4) * 8;
    const int bldr = wn * 32 + ((lane >> 4) & 1) * 8 + (lane & 7);   // + g*16
    const int bldc = ((lane >> 3) & 1) * 8;

    float acc[2][4][4];
    #pragma unroll
    for (int mi = 0; mi < 2; mi++)
        #pragma unroll
        for (int ni = 0; ni < 4; ni++)
            #pragma unroll
            for (int q = 0; q < 4; q++) acc[mi][ni][q] = 0.f;

    const int NC = INDIM / 16;   // 96

    // ---------------- pipeline lambdas (macros) ----------------
    #define QKV_STAGE_B(st, c) do {                                              \
        uint32_t dh = smem_u32(&(bop ? sBl : sBh)[st][brow][bhalf * 8]);         \
        cp16(dh, bsrc + (size_t)(n0 + brow) * INDIM + (c) * 16 + bhalf * 8);     \
    } while (0)

    #define QKV_LOAD_A(c, rv) do {                                               \
        int k = (c) * 16 + aseg * 4;                                             \
        rv = *(const float4*)(x + baseA + (long)(k >> 6) * 65536 + (k & 63));    \
    } while (0)

    #define STS_A(st, rv) do {                                                   \
        float r0, r1, r2, r3;                                                    \
        uint32_t h0 = hi2(rv.x, rv.y, r0, r1);                                   \
        uint32_t h1 = hi2(rv.z, rv.w, r2, r3);                                   \
        *(uint2*)&sAh[st][arow][aseg * 4] = make_uint2(h0, h1);                  \
        *(uint2*)&sAl[st][arow][aseg * 4] = make_uint2(lo2(r0, r1), lo2(r2, r3));\
    } while (0)

    // ---------------- prologue ----------------
    float4 rA;
    QKV_STAGE_B(0, 0); CP_COMMIT();
    QKV_LOAD_A(0, rA);
    STS_A(0, rA);
    QKV_STAGE_B(1, 1); CP_COMMIT();
    QKV_LOAD_A(1, rA);
    CP_WAIT(1);
    __syncthreads();

    for (int c = 0; c < NC; c++) {
        const int cur = c & 1;
        // ---- fragments ----
        uint32_t ah[2][4], al[2][4], bh[2][4], bl[2][4];
        #pragma unroll
        for (int mi = 0; mi < 2; mi++) {
            LDSM_X4(ah[mi], smem_u32(&sAh[cur][aldr + mi * 16][aldc]));
            LDSM_X4(al[mi], smem_u32(&sAl[cur][aldr + mi * 16][aldc]));
        }
        #pragma unroll
        for (int g = 0; g < 2; g++) {
            LDSM_X4(bh[g], smem_u32(&sBh[cur][bldr + g * 16][bldc]));
            LDSM_X4(bl[g], smem_u32(&sBl[cur][bldr + g * 16][bldc]));
        }
        // ---- 3-pass split MMA ----
        #pragma unroll
        for (int mi = 0; mi < 2; mi++)
            #pragma unroll
            for (int ni = 0; ni < 4; ni++) {
                uint32_t b0h = bh[ni >> 1][(ni & 1) * 2], b1h = bh[ni >> 1][(ni & 1) * 2 + 1];
                uint32_t b0l = bl[ni >> 1][(ni & 1) * 2], b1l = bl[ni >> 1][(ni & 1) * 2 + 1];
                mma16816(acc[mi][ni], ah[mi], b0h, b1h);
                mma16816(acc[mi][ni], ah[mi], b0l, b1l);
                mma16816(acc[mi][ni], al[mi], b0h, b1h);
            }
        // ---- pipeline maintenance ----
        if (c + 1 < NC) STS_A(cur ^ 1, rA);
        if (c + 2 < NC) QKV_LOAD_A(c + 2, rA);
        CP_WAIT(0);
        __syncthreads();
        if (c + 2 < NC) { QKV_STAGE_B(cur, c + 2); CP_COMMIT(); }
    }

    // ---- epilogue ----
    #pragma unroll
    for (int mi = 0; mi < 2; mi++) {
        int r = m0 + wm * 32 + mi * 16 + (lane >> 2);
        #pragma unroll
        for (int ni = 0; ni < 4; ni++) {
            int cg = n0 + wn * 32 + ni * 8 + (lane & 3) * 2;
            *(float2*)(C + (size_t)r * HID + cg)       = make_float2(acc[mi][ni][0], acc[mi][ni][1]);
            *(float2*)(C + (size_t)(r + 8) * HID + cg) = make_float2(acc[mi][ni][2], acc[mi][ni][3]);
        }
    }
    #undef QKV_STAGE_B
    #undef QKV_LOAD_A
    #undef STS_A
}

// =====================================================================
// Kernel 2: RoPE + tiny attention (unchanged).
// =====================================================================
__global__ __launch_bounds__(256)
void attn_kernel(const float* __restrict__ fcos, const float* __restrict__ fsin)
{
    __shared__ float sq[NSEG][HID];
    __shared__ float sk[NSEG][HID];
    __shared__ float sv[NSEG][HID];

    const int bhw = blockIdx.x;
    const int tid = threadIdx.x;
    const long base = (long)bhw * NSEG * HID;

    for (int idx = tid; idx < NSEG * (HID / 2); idx += 256) {
        int i = idx / (HID / 2);
        int j = idx - i * (HID / 2);
        float c = fcos[i * (HID / 2) + j];
        float s = fsin[i * (HID / 2) + j];
        float2 q2 = *(const float2*)(g_q + base + (long)i * HID + 2 * j);
        float2 k2 = *(const float2*)(g_k + base + (long)i * HID + 2 * j);
        sq[i][2 * j]     = q2.x * c - q2.y * s;
        sq[i][2 * j + 1] = q2.x * s + q2.y * c;
        sk[i][2 * j]     = k2.x * c - k2.y * s;
        sk[i][2 * j + 1] = k2.x * s + k2.y * c;
        float2 v2 = *(const float2*)(g_v + base + (long)i * HID + 2 * j);
        *(float2*)&sv[i][2 * j] = v2;
    }
    __syncthreads();

    const int w = tid >> 5;
    const int lane = tid & 31;
    const int cb = w * HD;

    float sc[4][4];
    #pragma unroll
    for (int i = 0; i < 4; i++)
        #pragma unroll
        for (int j = 0; j < 4; j++) {
            float p = 0.f;
            #pragma unroll
            for (int t = 0; t < 3; t++) {
                int d = lane + 32 * t;
                p += sq[i][cb + d] * sk[j][cb + d];
            }
            sc[i][j] = p;
        }
    #pragma unroll
    for (int i = 0; i < 4; i++)
        #pragma unroll
        for (int j = 0; j < 4; j++)
            #pragma unroll
            for (int off = 16; off > 0; off >>= 1)
                sc[i][j] += __shfl_xor_sync(0xffffffffu, sc[i][j], off);

    const float scale = 0.10206207261596577f;   // 1/sqrt(96)
    float attn[4][4];
    #pragma unroll
    for (int i = 0; i < 4; i++) {
        float mx = -1e30f;
        #pragma unroll
        for (int j = 0; j < 4; j++) { sc[i][j] *= scale; mx = fmaxf(mx, sc[i][j]); }
        float sum = 0.f;
        #pragma unroll
        for (int j = 0; j < 4; j++) { attn[i][j] = expf(sc[i][j] - mx); sum += attn[i][j]; }
        float inv = 1.f / sum;
        #pragma unroll
        for (int j = 0; j < 4; j++) attn[i][j] *= inv;
    }

    #pragma unroll
    for (int i = 0; i < 4; i++) {
        #pragma unroll
        for (int t = 0; t < 3; t++) {
            int d = lane + 32 * t;
            float o = 0.f;
            #pragma unroll
            for (int j = 0; j < 4; j++) o += attn[i][j] * sv[j][cb + d];
            g_o[base + (long)i * HID + cb + d] = o;
        }
    }
}

// =====================================================================
// Kernel 3: O-proj GEMM, mma.sync bf16 split-3.  grid (12, 256), block 512.
// Epilogue: + bias, scatter to (B,T,H,W,D).
// =====================================================================
__global__ __launch_bounds__(512, 1) void gemm_o_mma(const float* __restrict__ bo,
                                                     float* __restrict__ out)
{
    __shared__ __nv_bfloat16 sAh[2][128][24];
    __shared__ __nv_bfloat16 sAl[2][128][24];
    __shared__ __nv_bfloat16 sBh[2][128][24];
    __shared__ __nv_bfloat16 sBl[2][128][24];

    const int tid = threadIdx.x;
    const int n0 = blockIdx.x * 128, m0 = blockIdx.y * 128;

    const int arow = tid >> 2, aseg = tid & 3;
    const int bop = tid >> 8, brow = (tid & 255) >> 1, bhalf = tid & 1;
    const __nv_bfloat16* bsrc = bop ? g_wo_lo : g_wo_hi;

    const int wid = tid >> 5, lane = tid & 31;
    const int wm = wid & 3, wn = wid >> 2;
    const int aldr = wm * 32 + (lane & 15);
    const int aldc = (lane >> 4) * 8;
    const int bldr = wn * 32 + ((lane >> 4) & 1) * 8 + (lane & 7);
    const int bldc = ((lane >> 3) & 1) * 8;

    float acc[2][4][4];
    #pragma unroll
    for (int mi = 0; mi < 2; mi++)
        #pragma unroll
        for (int ni = 0; ni < 4; ni++)
            #pragma unroll
            for (int q = 0; q < 4; q++) acc[mi][ni][q] = 0.f;

    const int NC = HID / 16;   // 48

    #define O_STAGE_B(st, c) do {                                                \
        uint32_t dh = smem_u32(&(bop ? sBl : sBh)[st][brow][bhalf * 8]);         \
        cp16(dh, bsrc + (size_t)(n0 + brow) * HID + (c) * 16 + bhalf * 8);       \
    } while (0)

    #define O_LOAD_A(c, rv) \
        rv = *(const float4*)(g_o + (size_t)(m0 + arow) * HID + (c) * 16 + aseg * 4)

    #define STS_A(st, rv) do {                                                   \
        float r0, r1, r2, r3;                                                    \
        uint32_t h0 = hi2(rv.x, rv.y, r0, r1);                                   \
        uint32_t h1 = hi2(rv.z, rv.w, r2, r3);                                   \
        *(uint2*)&sAh[st][arow][aseg * 4] = make_uint2(h0, h1);                  \
        *(uint2*)&sAl[st][arow][aseg * 4] = make_uint2(lo2(r0, r1), lo2(r2, r3));\
    } while (0)

    float4 rA;
    O_STAGE_B(0, 0); CP_COMMIT();
    O_LOAD_A(0, rA);
    STS_A(0, rA);
    O_STAGE_B(1, 1); CP_COMMIT();
    O_LOAD_A(1, rA);
    CP_WAIT(1);
    __syncthreads();

    for (int c = 0; c < NC; c++) {
        const int cur = c & 1;
        uint32_t ah[2][4], al[2][4], bh[2][4], bl[2][4];
        #pragma unroll
        for (int mi = 0; mi < 2; mi++) {
            LDSM_X4(ah[mi], smem_u32(&sAh[cur][aldr + mi * 16][aldc]));
            LDSM_X4(al[mi], smem_u32(&sAl[cur][aldr + mi * 16][aldc]));
        }
        #pragma unroll
        for (int g = 0; g < 2; g++) {
            LDSM_X4(bh[g], smem_u32(&sBh[cur][bldr + g * 16][bldc]));
            LDSM_X4(bl[g], smem_u32(&sBl[cur][bldr + g * 16][bldc]));
        }
        #pragma unroll
        for (int mi = 0; mi < 2; mi++)
            #pragma unroll
            for (int ni = 0; ni < 4; ni++) {
                uint32_t b0h = bh[ni >> 1][(ni & 1) * 2], b1h = bh[ni >> 1][(ni & 1) * 2 + 1];
                uint32_t b0l = bl[ni >> 1][(ni & 1) * 2], b1l = bl[ni >> 1][(ni & 1) * 2 + 1];
                mma16816(acc[mi][ni], ah[mi], b0h, b1h);
                mma16816(acc[mi][ni], ah[mi], b0l, b1l);
                mma16816(acc[mi][ni], al[mi], b0h, b1h);
            }
        if (c + 1 < NC) STS_A(cur ^ 1, rA);
        if (c + 2 < NC) O_LOAD_A(c + 2, rA);
        CP_WAIT(0);
        __syncthreads();
        if (c + 2 < NC) { O_STAGE_B(cur, c + 2); CP_COMMIT(); }
    }

    // ---- epilogue: + bias, scatter ----
    #pragma unroll
    for (int mi = 0; mi < 2; mi++) {
        #pragma unroll
        for (int half = 0; half < 2; half++) {   // half: rows r, r+8
            int m = m0 + wm * 32 + mi * 16 + (lane >> 2) + half * 8;
            int bhw = m >> 2, sg = m & 3, b = bhw >> 10, hw = bhw & 1023;
            long baseO = ((long)(b * 96 + sg * 24) * 1024 + hw) * 64;
            #pragma unroll
            for (int ni = 0; ni < 4; ni++) {
                int e = n0 + wn * 32 + ni * 8 + (lane & 3) * 2;
                int p = e >> 6, d = e & 63;
                float2 bb = *(const float2*)(bo + e);
                float2 v = make_float2(acc[mi][ni][half * 2]     + bb.x,
                                       acc[mi][ni][half * 2 + 1] + bb.y);
                *(float2*)(out + baseO + (long)p * 65536 + d) = v;
            }
        }
    }
    #undef O_STAGE_B
    #undef O_LOAD_A
    #undef STS_A
}

// =====================================================================
extern "C" void kernel_launch(void* const* d_in, const int* in_sizes, int n_in,
                              void* d_out, int out_size)
{
    const float* x  = (const float*)d_in[0];
    const float* fc = (const float*)d_in[1];
    const float* fs = (const float*)d_in[2];
    const float* Wq = (const float*)d_in[3];
    const float* Wk = (const float*)d_in[4];
    const float* Wv = (const float*)d_in[5];
    const float* Wo = (const float*)d_in[6];
    const float* bo = (const float*)d_in[7];
    float* out = (float*)d_out;

    convert_qkv<<<dim3((HID * INDIM) / 256, 3), 256>>>(Wq, Wk, Wv);
    convert_wo<<<(INDIM * HID) / 256, 256>>>(Wo);
    gemm_qkv_mma<<<dim3(HID / 128, TOK / 128, 3), 512>>>(x);
    attn_kernel<<<BHW, 256>>>(fc, fs);
    gemm_o_mma<<<dim3(INDIM / 128, TOK / 128), 512>>>(bo, out);
}